// round 6
// baseline (speedup 1.0000x reference)
#include <cuda_runtime.h>
#include <cstdint>
#include <cstddef>

// Problem constants
#define N_TOT 131072   // B*S points
#define D_DIM 256      // feature dim
#define K_CL  512      // clusters

#define MT 128         // points per CTA tile
#define TAU 0.4f       // tf32 near-tie threshold (err-diff RMS ~0.022 -> ~18 sigma)

// ---- dynamic SMEM layout (bytes) ----
// X tile: [128][260] f32 (pre-converted tf32 bits; stride 260 = conflict-free)
#define XSTR 260
#define BSTR 36                        // C chunk row stride (32 dims + 4 pad)
#define SM_X   0                       // 133120 bytes
#define SM_B0  133120                  // C chunk buf0: [256][36] f32 = 36864
#define SM_B1  (SM_B0 + 36864)         // 169984
#define SM_C2  (SM_B1 + 36864)         // 206848: 512 f32
#define SM_BV  (SM_C2 + 2048)          // float[4][128]
#define SM_SV  (SM_BV + 2048)
#define SM_IV  (SM_SV + 2048)
#define SMEM_TOTAL (SM_IV + 2048)      // 215040

// Scratch (device globals — no allocation allowed)
__device__ int   g_idx[N_TOT];
__device__ int   g_rank[N_TOT];
__device__ int   g_order[N_TOT];
__device__ int   g_cnt2[K_CL];
__device__ int   g_off[K_CL];
__device__ float g_part[4][K_CL][D_DIM];   // gather partials (2 MB)
__device__ float g_c2[K_CL];
__device__ int   g_nref;
__device__ int   g_rlist[N_TOT];

// ---------------- portable PTX helpers (NO 'a'-gated features) -------------
__device__ __forceinline__ uint32_t smem_u32(const void* p) {
    uint32_t a;
    asm("{ .reg .u64 t; cvta.to.shared.u64 t, %1; cvt.u32.u64 %0, t; }"
        : "=r"(a) : "l"(p));
    return a;
}
__device__ __forceinline__ void cpa16(uint32_t dst, const void* src) {
    asm volatile("cp.async.cg.shared.global [%0], [%1], 16;"
                 :: "r"(dst), "l"(src) : "memory");
}
#define CP_COMMIT() asm volatile("cp.async.commit_group;" ::: "memory")
#define CP_WAIT(n)  asm volatile("cp.async.wait_group %0;" :: "n"(n) : "memory")

__device__ __forceinline__ uint32_t f2tf(float f) {
    uint32_t r;
    asm("cvt.rna.tf32.f32 %0, %1;" : "=r"(r) : "f"(f));
    return r;
}
__device__ __forceinline__ void mma8(float* d, const uint32_t* a, const uint32_t* b) {
    asm volatile(
        "mma.sync.aligned.m16n8k8.row.col.f32.tf32.tf32.f32 "
        "{%0,%1,%2,%3}, {%4,%5,%6,%7}, {%8,%9}, {%0,%1,%2,%3};"
        : "+f"(d[0]), "+f"(d[1]), "+f"(d[2]), "+f"(d[3])
        : "r"(a[0]), "r"(a[1]), "r"(a[2]), "r"(a[3]), "r"(b[0]), "r"(b[1]));
}

// ---------------------------------------------------------------------------
// init: zero refine/rank counters, c2[k] = sum_d C[k][d]^2 (fp64->fp32)
// ---------------------------------------------------------------------------
__global__ void init_kernel(const float* __restrict__ C) {
    int t = blockIdx.x * blockDim.x + threadIdx.x;
    if (t == 0) g_nref = 0;
    if (t < K_CL) {
        g_cnt2[t] = 0;
        const float4* c = (const float4*)(C + (size_t)t * D_DIM);
        double s = 0.0;
        #pragma unroll
        for (int j = 0; j < D_DIM / 4; ++j) {
            float4 v = c[j];
            s += (double)v.x * v.x + (double)v.y * v.y
               + (double)v.z * v.z + (double)v.w * v.w;
        }
        g_c2[t] = (float)s;
    }
}

// ---------------------------------------------------------------------------
// C chunk loader: C[kt .. kt+256)[db .. db+32) -> smem [256][BSTR]
// ---------------------------------------------------------------------------
__device__ __forceinline__ void load_cchunk(const float* __restrict__ C,
                                            uint32_t base, int kt, int db,
                                            int tid) {
    #pragma unroll
    for (int i = 0; i < 8; ++i) {
        int idx = i * 256 + tid;
        int r = idx >> 3, s = idx & 7;
        cpa16(base + r * (BSTR * 4) + s * 16,
              C + (size_t)(kt + r) * D_DIM + db + s * 4);
    }
}

// ---------------------------------------------------------------------------
// mma.sync tf32 fused distance-GEMM + top-2 argmin per 128-point tile.
// 64x64 warp tiles (2m x 4n warp grid over 128 rows x 256 clusters, 2 k-passes).
// Streams each point's full one-hot row (no separate memset).
// ---------------------------------------------------------------------------
__global__ __launch_bounds__(256, 1)
void argmin_mma(const float* __restrict__ X, const float* __restrict__ C,
                float* __restrict__ out) {
    extern __shared__ char smem[];
    const uint32_t sb = smem_u32(smem);
    const int tid  = threadIdx.x;
    const int wid  = tid >> 5, lane = tid & 31;
    const int qrow = lane >> 2, qcol = lane & 3;
    const int wm   = wid & 1,  wn   = wid >> 1;   // 2m x 4n warp grid
    const int RM   = wm * 64,  CN   = wn * 64;
    const int n0   = blockIdx.x * MT;

    float* Xs  = (float*)(smem + SM_X);
    float* c2s = (float*)(smem + SM_C2);
    float* bvS = (float*)(smem + SM_BV);
    float* svS = (float*)(smem + SM_SV);
    int*   ivS = (int*)  (smem + SM_IV);

    // kick off first two C chunks (async)
    load_cchunk(C, sb + SM_B0, 0, 0, tid);  CP_COMMIT();
    load_cchunk(C, sb + SM_B1, 0, 32, tid); CP_COMMIT();

    // stage c2
    c2s[tid]       = g_c2[tid];
    c2s[tid + 256] = g_c2[tid + 256];

    // X tile: LDG -> tf32 convert -> STS (same layout as proven R4 kernel)
    #pragma unroll
    for (int i = 0; i < 32; ++i) {
        int idx = i * 256 + tid;
        int r = idx >> 6, s = idx & 63;
        float4 v = *(const float4*)(X + (size_t)(n0 + r) * D_DIM + s * 4);
        float4 w;
        w.x = __uint_as_float(f2tf(v.x));
        w.y = __uint_as_float(f2tf(v.y));
        w.z = __uint_as_float(f2tf(v.z));
        w.w = __uint_as_float(f2tf(v.w));
        *(float4*)(Xs + r * XSTR + s * 4) = w;
    }
    CP_WAIT(1);           // chunk0 ready
    __syncthreads();

    float acc[4][8][4];
    #pragma unroll
    for (int a = 0; a < 4; ++a)
        #pragma unroll
        for (int b = 0; b < 8; ++b)
            #pragma unroll
            for (int c = 0; c < 4; ++c) acc[a][b][c] = 0.0f;

    float best[8], sec[8];
    int   idx8[8];
    #pragma unroll
    for (int t = 0; t < 8; ++t) { best[t] = 3.4e38f; sec[t] = 3.4e38f; idx8[t] = 0; }

    for (int q = 0; q < 16; ++q) {
        const int sbuf = q & 1;
        const int db   = (q & 7) * 32;
        const float* Bs = (const float*)(smem + (sbuf ? SM_B1 : SM_B0));

        #pragma unroll
        for (int ks = 0; ks < 4; ++ks) {
            const int dX = db + ks * 8 + qcol;
            uint32_t Af[4][4];
            #pragma unroll
            for (int mt = 0; mt < 4; ++mt) {
                int r = RM + mt * 16 + qrow;
                Af[mt][0] = __float_as_uint(Xs[r * XSTR + dX]);
                Af[mt][1] = __float_as_uint(Xs[(r + 8) * XSTR + dX]);
                Af[mt][2] = __float_as_uint(Xs[r * XSTR + dX + 4]);
                Af[mt][3] = __float_as_uint(Xs[(r + 8) * XSTR + dX + 4]);
            }
            uint32_t Bf[8][2];
            #pragma unroll
            for (int nt = 0; nt < 8; ++nt) {
                int n = CN + nt * 8 + qrow;
                Bf[nt][0] = f2tf(Bs[n * BSTR + ks * 8 + qcol]);
                Bf[nt][1] = f2tf(Bs[n * BSTR + ks * 8 + 4 + qcol]);
            }
            #pragma unroll
            for (int mt = 0; mt < 4; ++mt)
                #pragma unroll
                for (int nt = 0; nt < 8; ++nt)
                    mma8(acc[mt][nt], Af[mt], Bf[nt]);
        }

        if ((q & 7) == 7) {
            // pass epilogue: score = c2 - 2*dot, update per-slot top-2, zero acc
            const int kt = (q >> 3) * 256;
            #pragma unroll
            for (int mt = 0; mt < 4; ++mt) {
                #pragma unroll
                for (int nt = 0; nt < 8; ++nt) {
                    int k0 = kt + CN + nt * 8 + 2 * qcol;
                    float c20 = c2s[k0], c21 = c2s[k0 + 1];
                    float s0 = fmaf(-2.0f, acc[mt][nt][0], c20);
                    float s1 = fmaf(-2.0f, acc[mt][nt][1], c21);
                    float s2 = fmaf(-2.0f, acc[mt][nt][2], c20);
                    float s3 = fmaf(-2.0f, acc[mt][nt][3], c21);
                    int t0 = mt * 2, t1 = mt * 2 + 1;
                    if (s0 < sec[t0]) { if (s0 < best[t0]) { sec[t0] = best[t0]; best[t0] = s0; idx8[t0] = k0; } else sec[t0] = s0; }
                    if (s1 < sec[t0]) { if (s1 < best[t0]) { sec[t0] = best[t0]; best[t0] = s1; idx8[t0] = k0 + 1; } else sec[t0] = s1; }
                    if (s2 < sec[t1]) { if (s2 < best[t1]) { sec[t1] = best[t1]; best[t1] = s2; idx8[t1] = k0; } else sec[t1] = s2; }
                    if (s3 < sec[t1]) { if (s3 < best[t1]) { sec[t1] = best[t1]; best[t1] = s3; idx8[t1] = k0 + 1; } else sec[t1] = s3; }
                    acc[mt][nt][0] = 0.0f; acc[mt][nt][1] = 0.0f;
                    acc[mt][nt][2] = 0.0f; acc[mt][nt][3] = 0.0f;
                }
            }
        }

        __syncthreads();                       // all warps done reading buf sbuf
        if (q + 2 < 16) {
            int q2 = q + 2;
            load_cchunk(C, sb + (sbuf ? SM_B1 : SM_B0),
                        (q2 >> 3) * 256, (q2 & 7) * 32, tid);
            CP_COMMIT();
            CP_WAIT(1);                        // chunk q+1 ready
        } else if (q == 14) {
            CP_WAIT(0);                        // last chunk ready
        }
        if (q < 15) __syncthreads();
    }

    // quad merge (lanes differing in qcol share rows)
    #pragma unroll
    for (int t = 0; t < 8; ++t) {
        float b = best[t], s = sec[t];
        int   i = idx8[t];
        #pragma unroll
        for (int o = 1; o <= 2; o <<= 1) {
            float b2 = __shfl_xor_sync(0xFFFFFFFFu, b, o);
            float s2 = __shfl_xor_sync(0xFFFFFFFFu, s, o);
            int   i2 = __shfl_xor_sync(0xFFFFFFFFu, i, o);
            if (b2 < b || (b2 == b && i2 < i)) { s = fminf(b, s2); b = b2; i = i2; }
            else                               { s = fminf(s, b2); }
        }
        if (qcol == 0) {
            int row = RM + (t >> 1) * 16 + qrow + (t & 1) * 8;
            bvS[wn * 128 + row] = b;
            svS[wn * 128 + row] = s;
            ivS[wn * 128 + row] = i;
        }
    }
    __syncthreads();

    // final cross-warp merge + decision (one thread per point)
    if (tid < 128) {
        float bb = bvS[tid], ss = svS[tid];
        int   ii = ivS[tid];
        #pragma unroll
        for (int w = 1; w < 4; ++w) {
            float b2 = bvS[w * 128 + tid], s2 = svS[w * 128 + tid];
            int   i2 = ivS[w * 128 + tid];
            if (b2 < bb || (b2 == bb && i2 < ii)) { ss = fminf(bb, s2); bb = b2; ii = i2; }
            else                                   { ss = fminf(ss, b2); }
        }
        int n = n0 + tid;
        g_idx[n] = ii;
        int mark = ii;
        if (ss - bb < TAU) {
            int slot = atomicAdd(&g_nref, 1);
            g_rlist[slot] = n;
            mark = -1;                      // refine writes the 1.0 later
        }
        ivS[tid] = mark;
    }
    __syncthreads();

    // stream full one-hot rows (replaces global memset)
    #pragma unroll
    for (int i = 0; i < 64; ++i) {
        int idx = i * 256 + tid;
        int row = idx >> 7, s = idx & 127;
        int m = ivS[row];
        float4 v = make_float4(0.f, 0.f, 0.f, 0.f);
        if ((m >> 2) == s) ((float*)&v)[m & 3] = 1.0f;
        __stcs((float4*)(out + (size_t)(n0 + row) * K_CL + s * 4), v);
    }
}

// ---------------------------------------------------------------------------
// refine: near-tie points -> all-K distances via Kahan fp32 dot, reference
// rounding order fl(fl(x2 - 2*dot) + c2), first-index tie-break.
// ---------------------------------------------------------------------------
__device__ __forceinline__ void kadd(float& s, float& comp, float t) {
    float y = __fsub_rn(t, comp);
    float u = __fadd_rn(s, y);
    comp = __fsub_rn(__fsub_rn(u, s), y);
    s = u;
}

__global__ __launch_bounds__(256)
void refine_kernel(const float* __restrict__ X, const float* __restrict__ C,
                   float* __restrict__ out) {
    __shared__ float  xsh[D_DIM];
    __shared__ double xwr[8];
    __shared__ float  x2sh;
    __shared__ float  rv[256];
    __shared__ int    ri[256];

    const int tid  = threadIdx.x;
    const int nref = g_nref;

    for (int it = blockIdx.x; it < nref; it += gridDim.x) {
        const int n = g_rlist[it];
        __syncthreads();
        xsh[tid] = X[(size_t)n * D_DIM + tid];
        __syncthreads();
        {
            double p = (double)xsh[tid] * (double)xsh[tid];
            #pragma unroll
            for (int o = 16; o >= 1; o >>= 1)
                p += __shfl_xor_sync(0xFFFFFFFFu, p, o);
            if ((tid & 31) == 0) xwr[tid >> 5] = p;
            __syncthreads();
            if (tid == 0) {
                double t = 0.0;
                #pragma unroll
                for (int w = 0; w < 8; ++w) t += xwr[w];
                x2sh = (float)t;
            }
            __syncthreads();
        }
        const float x2f = x2sh;
        const float4* xs4 = (const float4*)xsh;

        float bv = 3.4e38f;
        int   bi = 0x7fffffff;
        #pragma unroll
        for (int kk = 0; kk < 2; ++kk) {
            const int k = 2 * tid + kk;
            const float4* cp = (const float4*)(C + (size_t)k * D_DIM);
            float s = 0.0f, comp = 0.0f;
            #pragma unroll 4
            for (int j = 0; j < D_DIM / 4; ++j) {
                float4 cv = cp[j];
                float4 xv = xs4[j];
                kadd(s, comp, __fmul_rn(cv.x, xv.x));
                kadd(s, comp, __fmul_rn(cv.y, xv.y));
                kadd(s, comp, __fmul_rn(cv.z, xv.z));
                kadd(s, comp, __fmul_rn(cv.w, xv.w));
            }
            float dotf = __fadd_rn(s, comp);
            float m = __fmul_rn(2.0f, dotf);
            float a = __fsub_rn(x2f, m);
            float dist = __fadd_rn(a, g_c2[k]);
            if (dist < bv || (dist == bv && k < bi)) { bv = dist; bi = k; }
        }
        rv[tid] = bv; ri[tid] = bi;
        __syncthreads();
        #pragma unroll
        for (int st = 128; st > 0; st >>= 1) {
            if (tid < st) {
                float ov = rv[tid + st]; int oi = ri[tid + st];
                if (ov < rv[tid] || (ov == rv[tid] && oi < ri[tid])) {
                    rv[tid] = ov; ri[tid] = oi;
                }
            }
            __syncthreads();
        }
        if (tid == 0) {
            g_idx[n] = ri[0];
            out[(size_t)n * K_CL + ri[0]] = 1.0f;   // row already all-zero
        }
    }
}

// ---------------------------------------------------------------------------
// sort-based accumulation (no sum atomics)
// ---------------------------------------------------------------------------
__global__ void rank_kernel() {
    int n = blockIdx.x * blockDim.x + threadIdx.x;
    if (n >= N_TOT) return;
    g_rank[n] = atomicAdd(&g_cnt2[g_idx[n]], 1);
}

__global__ void scan_kernel() {
    __shared__ int s[K_CL];
    int tid = threadIdx.x;
    s[tid] = g_cnt2[tid];
    __syncthreads();
    #pragma unroll
    for (int off = 1; off < K_CL; off <<= 1) {
        int v = (tid >= off) ? s[tid - off] : 0;
        __syncthreads();
        s[tid] += v;
        __syncthreads();
    }
    g_off[tid] = s[tid] - g_cnt2[tid];   // exclusive
}

__global__ void scatter_kernel() {
    int n = blockIdx.x * blockDim.x + threadIdx.x;
    if (n >= N_TOT) return;
    g_order[g_off[g_idx[n]] + g_rank[n]] = n;
}

__global__ __launch_bounds__(256)
void gather_kernel(const float* __restrict__ X) {
    const int c  = blockIdx.x >> 2;
    const int qu = blockIdx.x & 3;
    const int d  = threadIdx.x;
    const int cnt  = g_cnt2[c];
    const int base = g_off[c];
    int beg = base + (cnt * qu) / 4;
    int end = base + (cnt * (qu + 1)) / 4;
    float a0 = 0.f, a1 = 0.f, a2 = 0.f, a3 = 0.f;
    int i = beg;
    for (; i + 3 < end; i += 4) {
        int n0 = g_order[i], n1 = g_order[i + 1];
        int n2 = g_order[i + 2], n3 = g_order[i + 3];
        a0 += X[(size_t)n0 * D_DIM + d];
        a1 += X[(size_t)n1 * D_DIM + d];
        a2 += X[(size_t)n2 * D_DIM + d];
        a3 += X[(size_t)n3 * D_DIM + d];
    }
    for (; i < end; ++i) a0 += X[(size_t)g_order[i] * D_DIM + d];
    g_part[qu][c][d] = (a0 + a1) + (a2 + a3);
}

__global__ void finalize_kernel(const float* __restrict__ C, float* __restrict__ outc) {
    int t = blockIdx.x * blockDim.x + threadIdx.x;
    if (t >= K_CL * D_DIM) return;
    int k = t >> 8, d = t & 255;
    float cnt = (float)g_cnt2[k];
    float sum = (g_part[0][k][d] + g_part[1][k][d])
              + (g_part[2][k][d] + g_part[3][k][d]);
    outc[t] = fmaf(0.9f, C[t], 0.1f * (sum / cnt));
}

// ---------------------------------------------------------------------------
extern "C" void kernel_launch(void* const* d_in, const int* in_sizes, int n_in,
                              void* d_out, int out_size) {
    const float* X = (const float*)d_in[0];
    const float* C = (const float*)d_in[1];
    float* out = (float*)d_out;
    (void)in_sizes; (void)n_in; (void)out_size;

    cudaFuncSetAttribute(argmin_mma, cudaFuncAttributeMaxDynamicSharedMemorySize,
                         SMEM_TOTAL);

    init_kernel<<<2, 256>>>(C);
    argmin_mma<<<N_TOT / MT, 256, SMEM_TOTAL>>>(X, C, out);
    refine_kernel<<<1024, 256>>>(X, C, out);
    rank_kernel<<<N_TOT / 256, 256>>>();
    scan_kernel<<<1, K_CL>>>();
    scatter_kernel<<<N_TOT / 256, 256>>>();
    gather_kernel<<<K_CL * 4, 256>>>(X);
    finalize_kernel<<<(K_CL * D_DIM) / 256, 256>>>(C, out + (size_t)N_TOT * K_CL);
}

// round 7
// speedup vs baseline: 1.0093x; 1.0093x over previous
#include <cuda_runtime.h>
#include <cstdint>
#include <cstddef>

// Problem constants
#define N_TOT 131072   // B*S points
#define D_DIM 256      // feature dim
#define K_CL  512      // clusters

#define MT 64          // points per CTA tile (halved -> occupancy 2)
#define TAU 0.4f       // tf32 near-tie threshold (err-diff RMS ~0.022 -> ~18 sigma)

// ---- dynamic SMEM layout (bytes) ----
// X tile: [64][260] f32 (pre-converted tf32 bits; stride 260 = conflict-free)
#define XSTR 260
#define BSTR 36                        // C chunk row stride (32 dims + 4 pad)
#define SM_X   0                       // 66560 bytes
#define SM_B0  66560                   // C chunk buf0: [128][36] f32 = 18432
#define SM_B1  (SM_B0 + 18432)         // 84992
#define SM_C2  (SM_B1 + 18432)         // 103424: 512 f32
#define SM_BV  (SM_C2 + 2048)          // float[4][64]
#define SM_SV  (SM_BV + 1024)
#define SM_IV  (SM_SV + 1024)
#define SMEM_TOTAL (SM_IV + 1024)      // 108544  (x2 CTAs = 217088 < 228KB)

// Scratch (device globals — no allocation allowed)
__device__ int   g_idx[N_TOT];
__device__ int   g_rank[N_TOT];
__device__ int   g_order[N_TOT];
__device__ int   g_cnt2[K_CL];
__device__ int   g_off[K_CL];
__device__ float g_part[4][K_CL][D_DIM];   // gather partials (2 MB)
__device__ float g_c2[K_CL];
__device__ int   g_nref;
__device__ int   g_rlist[N_TOT];

// ---------------- portable PTX helpers (NO 'a'-gated features) -------------
__device__ __forceinline__ uint32_t smem_u32(const void* p) {
    uint32_t a;
    asm("{ .reg .u64 t; cvta.to.shared.u64 t, %1; cvt.u32.u64 %0, t; }"
        : "=r"(a) : "l"(p));
    return a;
}
__device__ __forceinline__ void cpa16(uint32_t dst, const void* src) {
    asm volatile("cp.async.cg.shared.global [%0], [%1], 16;"
                 :: "r"(dst), "l"(src) : "memory");
}
#define CP_COMMIT() asm volatile("cp.async.commit_group;" ::: "memory")
#define CP_WAIT(n)  asm volatile("cp.async.wait_group %0;" :: "n"(n) : "memory")

__device__ __forceinline__ uint32_t f2tf(float f) {
    uint32_t r;
    asm("cvt.rna.tf32.f32 %0, %1;" : "=r"(r) : "f"(f));
    return r;
}
__device__ __forceinline__ void mma8(float* d, const uint32_t* a, const uint32_t* b) {
    asm volatile(
        "mma.sync.aligned.m16n8k8.row.col.f32.tf32.tf32.f32 "
        "{%0,%1,%2,%3}, {%4,%5,%6,%7}, {%8,%9}, {%0,%1,%2,%3};"
        : "+f"(d[0]), "+f"(d[1]), "+f"(d[2]), "+f"(d[3])
        : "r"(a[0]), "r"(a[1]), "r"(a[2]), "r"(a[3]), "r"(b[0]), "r"(b[1]));
}

// ---------------------------------------------------------------------------
// init: zero refine/rank counters, c2[k] = sum_d C[k][d]^2 (fp64->fp32)
// ---------------------------------------------------------------------------
__global__ void init_kernel(const float* __restrict__ C) {
    int t = blockIdx.x * blockDim.x + threadIdx.x;
    if (t == 0) g_nref = 0;
    if (t < K_CL) {
        g_cnt2[t] = 0;
        const float4* c = (const float4*)(C + (size_t)t * D_DIM);
        double s = 0.0;
        #pragma unroll
        for (int j = 0; j < D_DIM / 4; ++j) {
            float4 v = c[j];
            s += (double)v.x * v.x + (double)v.y * v.y
               + (double)v.z * v.z + (double)v.w * v.w;
        }
        g_c2[t] = (float)s;
    }
}

// ---------------------------------------------------------------------------
// C chunk loader: C[kt .. kt+128)[db .. db+32) -> smem [128][BSTR]
// ---------------------------------------------------------------------------
__device__ __forceinline__ void load_cchunk(const float* __restrict__ C,
                                            uint32_t base, int kt, int db,
                                            int tid) {
    #pragma unroll
    for (int i = 0; i < 4; ++i) {
        int idx = i * 256 + tid;
        int r = idx >> 3, s = idx & 7;
        cpa16(base + r * (BSTR * 4) + s * 16,
              C + (size_t)(kt + r) * D_DIM + db + s * 4);
    }
}

// ---------------------------------------------------------------------------
// mma.sync tf32 fused distance-GEMM + top-2 argmin per 64-point tile.
// 32x32 warp tiles (2m x 4n grid over 64 rows x 128 clusters), 4 k-passes.
// Occupancy 2 CTAs/SM for latency hiding. Streams full one-hot rows.
// ---------------------------------------------------------------------------
__global__ __launch_bounds__(256, 2)
void argmin_mma(const float* __restrict__ X, const float* __restrict__ C,
                float* __restrict__ out) {
    extern __shared__ char smem[];
    const uint32_t sb = smem_u32(smem);
    const int tid  = threadIdx.x;
    const int wid  = tid >> 5, lane = tid & 31;
    const int qrow = lane >> 2, qcol = lane & 3;
    const int wm   = wid & 1,  wn   = wid >> 1;   // 2m x 4n warp grid
    const int RM   = wm * 32,  CN   = wn * 32;
    const int n0   = blockIdx.x * MT;

    float* Xs  = (float*)(smem + SM_X);
    float* c2s = (float*)(smem + SM_C2);
    float* bvS = (float*)(smem + SM_BV);
    float* svS = (float*)(smem + SM_SV);
    int*   ivS = (int*)  (smem + SM_IV);

    // kick off first two C chunks (async)
    load_cchunk(C, sb + SM_B0, 0, 0, tid);  CP_COMMIT();
    load_cchunk(C, sb + SM_B1, 0, 32, tid); CP_COMMIT();

    // stage c2
    c2s[tid]       = g_c2[tid];
    c2s[tid + 256] = g_c2[tid + 256];

    // X tile: LDG -> tf32 convert -> STS (same layout/indices as R4)
    #pragma unroll
    for (int i = 0; i < 16; ++i) {
        int idx = i * 256 + tid;
        int r = idx >> 6, s = idx & 63;
        float4 v = *(const float4*)(X + (size_t)(n0 + r) * D_DIM + s * 4);
        float4 w;
        w.x = __uint_as_float(f2tf(v.x));
        w.y = __uint_as_float(f2tf(v.y));
        w.z = __uint_as_float(f2tf(v.z));
        w.w = __uint_as_float(f2tf(v.w));
        *(float4*)(Xs + r * XSTR + s * 4) = w;
    }
    CP_WAIT(1);           // chunk0 ready
    __syncthreads();

    float acc[2][4][4];
    #pragma unroll
    for (int a = 0; a < 2; ++a)
        #pragma unroll
        for (int b = 0; b < 4; ++b)
            #pragma unroll
            for (int c = 0; c < 4; ++c) acc[a][b][c] = 0.0f;

    float best[4], sec[4];
    int   idx4[4];
    #pragma unroll
    for (int t = 0; t < 4; ++t) { best[t] = 3.4e38f; sec[t] = 3.4e38f; idx4[t] = 0; }

    // 32 chunks: kp = q>>3 selects 128-cluster pass, dc = q&7 selects 32-dim slice
    for (int q = 0; q < 32; ++q) {
        const int sbuf = q & 1;
        const int dc   = q & 7;
        const float* Bs = (const float*)(smem + (sbuf ? SM_B1 : SM_B0));

        #pragma unroll
        for (int ks = 0; ks < 4; ++ks) {
            const int dX = dc * 32 + ks * 8 + qcol;
            uint32_t Af[2][4];
            #pragma unroll
            for (int mt = 0; mt < 2; ++mt) {
                int r = RM + mt * 16 + qrow;
                Af[mt][0] = __float_as_uint(Xs[r * XSTR + dX]);
                Af[mt][1] = __float_as_uint(Xs[(r + 8) * XSTR + dX]);
                Af[mt][2] = __float_as_uint(Xs[r * XSTR + dX + 4]);
                Af[mt][3] = __float_as_uint(Xs[(r + 8) * XSTR + dX + 4]);
            }
            uint32_t Bf[4][2];
            #pragma unroll
            for (int nt = 0; nt < 4; ++nt) {
                int n = CN + nt * 8 + qrow;
                Bf[nt][0] = f2tf(Bs[n * BSTR + ks * 8 + qcol]);
                Bf[nt][1] = f2tf(Bs[n * BSTR + ks * 8 + 4 + qcol]);
            }
            #pragma unroll
            for (int mt = 0; mt < 2; ++mt)
                #pragma unroll
                for (int nt = 0; nt < 4; ++nt)
                    mma8(acc[mt][nt], Af[mt], Bf[nt]);
        }

        if (dc == 7) {
            // pass epilogue: score = c2 - 2*dot, per-slot top-2, zero acc
            const int kt = (q >> 3) * 128;
            #pragma unroll
            for (int mt = 0; mt < 2; ++mt) {
                #pragma unroll
                for (int nt = 0; nt < 4; ++nt) {
                    int k0 = kt + CN + nt * 8 + 2 * qcol;
                    float c20 = c2s[k0], c21 = c2s[k0 + 1];
                    float s0 = fmaf(-2.0f, acc[mt][nt][0], c20);
                    float s1 = fmaf(-2.0f, acc[mt][nt][1], c21);
                    float s2 = fmaf(-2.0f, acc[mt][nt][2], c20);
                    float s3 = fmaf(-2.0f, acc[mt][nt][3], c21);
                    int t0 = mt * 2, t1 = mt * 2 + 1;
                    if (s0 < sec[t0]) { if (s0 < best[t0]) { sec[t0] = best[t0]; best[t0] = s0; idx4[t0] = k0; } else sec[t0] = s0; }
                    if (s1 < sec[t0]) { if (s1 < best[t0]) { sec[t0] = best[t0]; best[t0] = s1; idx4[t0] = k0 + 1; } else sec[t0] = s1; }
                    if (s2 < sec[t1]) { if (s2 < best[t1]) { sec[t1] = best[t1]; best[t1] = s2; idx4[t1] = k0; } else sec[t1] = s2; }
                    if (s3 < sec[t1]) { if (s3 < best[t1]) { sec[t1] = best[t1]; best[t1] = s3; idx4[t1] = k0 + 1; } else sec[t1] = s3; }
                    acc[mt][nt][0] = 0.0f; acc[mt][nt][1] = 0.0f;
                    acc[mt][nt][2] = 0.0f; acc[mt][nt][3] = 0.0f;
                }
            }
        }

        __syncthreads();                       // all warps done reading buf sbuf
        if (q + 2 < 32) {
            int q2 = q + 2;
            load_cchunk(C, sb + (sbuf ? SM_B1 : SM_B0),
                        (q2 >> 3) * 128, (q2 & 7) * 32, tid);
            CP_COMMIT();
            CP_WAIT(1);                        // chunk q+1 ready
        } else if (q == 30) {
            CP_WAIT(0);                        // last chunk ready
        }
        if (q < 31) __syncthreads();
    }

    // quad merge (lanes differing in qcol share rows)
    #pragma unroll
    for (int t = 0; t < 4; ++t) {
        float b = best[t], s = sec[t];
        int   i = idx4[t];
        #pragma unroll
        for (int o = 1; o <= 2; o <<= 1) {
            float b2 = __shfl_xor_sync(0xFFFFFFFFu, b, o);
            float s2 = __shfl_xor_sync(0xFFFFFFFFu, s, o);
            int   i2 = __shfl_xor_sync(0xFFFFFFFFu, i, o);
            if (b2 < b || (b2 == b && i2 < i)) { s = fminf(b, s2); b = b2; i = i2; }
            else                               { s = fminf(s, b2); }
        }
        if (qcol == 0) {
            int row = RM + (t >> 1) * 16 + qrow + (t & 1) * 8;
            bvS[wn * 64 + row] = b;
            svS[wn * 64 + row] = s;
            ivS[wn * 64 + row] = i;
        }
    }
    __syncthreads();

    // final cross-warp merge + decision (one thread per point)
    if (tid < 64) {
        float bb = bvS[tid], ss = svS[tid];
        int   ii = ivS[tid];
        #pragma unroll
        for (int w = 1; w < 4; ++w) {
            float b2 = bvS[w * 64 + tid], s2 = svS[w * 64 + tid];
            int   i2 = ivS[w * 64 + tid];
            if (b2 < bb || (b2 == bb && i2 < ii)) { ss = fminf(bb, s2); bb = b2; ii = i2; }
            else                                   { ss = fminf(ss, b2); }
        }
        int n = n0 + tid;
        g_idx[n] = ii;
        int mark = ii;
        if (ss - bb < TAU) {
            int slot = atomicAdd(&g_nref, 1);
            g_rlist[slot] = n;
            mark = -1;                      // refine writes the 1.0 later
        }
        ivS[tid] = mark;
    }
    __syncthreads();

    // stream full one-hot rows (replaces global memset)
    #pragma unroll
    for (int i = 0; i < 32; ++i) {
        int idx = i * 256 + tid;
        int row = idx >> 7, s = idx & 127;
        int m = ivS[row];
        float4 v = make_float4(0.f, 0.f, 0.f, 0.f);
        if ((m >> 2) == s) ((float*)&v)[m & 3] = 1.0f;
        __stcs((float4*)(out + (size_t)(n0 + row) * K_CL + s * 4), v);
    }
}

// ---------------------------------------------------------------------------
// refine: near-tie points -> all-K distances via Kahan fp32 dot, reference
// rounding order fl(fl(x2 - 2*dot) + c2), first-index tie-break.
// ---------------------------------------------------------------------------
__device__ __forceinline__ void kadd(float& s, float& comp, float t) {
    float y = __fsub_rn(t, comp);
    float u = __fadd_rn(s, y);
    comp = __fsub_rn(__fsub_rn(u, s), y);
    s = u;
}

__global__ __launch_bounds__(256)
void refine_kernel(const float* __restrict__ X, const float* __restrict__ C,
                   float* __restrict__ out) {
    __shared__ float  xsh[D_DIM];
    __shared__ double xwr[8];
    __shared__ float  x2sh;
    __shared__ float  rv[256];
    __shared__ int    ri[256];

    const int tid  = threadIdx.x;
    const int nref = g_nref;

    for (int it = blockIdx.x; it < nref; it += gridDim.x) {
        const int n = g_rlist[it];
        __syncthreads();
        xsh[tid] = X[(size_t)n * D_DIM + tid];
        __syncthreads();
        {
            double p = (double)xsh[tid] * (double)xsh[tid];
            #pragma unroll
            for (int o = 16; o >= 1; o >>= 1)
                p += __shfl_xor_sync(0xFFFFFFFFu, p, o);
            if ((tid & 31) == 0) xwr[tid >> 5] = p;
            __syncthreads();
            if (tid == 0) {
                double t = 0.0;
                #pragma unroll
                for (int w = 0; w < 8; ++w) t += xwr[w];
                x2sh = (float)t;
            }
            __syncthreads();
        }
        const float x2f = x2sh;
        const float4* xs4 = (const float4*)xsh;

        float bv = 3.4e38f;
        int   bi = 0x7fffffff;
        #pragma unroll
        for (int kk = 0; kk < 2; ++kk) {
            const int k = 2 * tid + kk;
            const float4* cp = (const float4*)(C + (size_t)k * D_DIM);
            float s = 0.0f, comp = 0.0f;
            #pragma unroll 4
            for (int j = 0; j < D_DIM / 4; ++j) {
                float4 cv = cp[j];
                float4 xv = xs4[j];
                kadd(s, comp, __fmul_rn(cv.x, xv.x));
                kadd(s, comp, __fmul_rn(cv.y, xv.y));
                kadd(s, comp, __fmul_rn(cv.z, xv.z));
                kadd(s, comp, __fmul_rn(cv.w, xv.w));
            }
            float dotf = __fadd_rn(s, comp);
            float m = __fmul_rn(2.0f, dotf);
            float a = __fsub_rn(x2f, m);
            float dist = __fadd_rn(a, g_c2[k]);
            if (dist < bv || (dist == bv && k < bi)) { bv = dist; bi = k; }
        }
        rv[tid] = bv; ri[tid] = bi;
        __syncthreads();
        #pragma unroll
        for (int st = 128; st > 0; st >>= 1) {
            if (tid < st) {
                float ov = rv[tid + st]; int oi = ri[tid + st];
                if (ov < rv[tid] || (ov == rv[tid] && oi < ri[tid])) {
                    rv[tid] = ov; ri[tid] = oi;
                }
            }
            __syncthreads();
        }
        if (tid == 0) {
            g_idx[n] = ri[0];
            out[(size_t)n * K_CL + ri[0]] = 1.0f;   // row already all-zero
        }
    }
}

// ---------------------------------------------------------------------------
// sort-based accumulation (no sum atomics)
// ---------------------------------------------------------------------------
__global__ void rank_kernel() {
    int n = blockIdx.x * blockDim.x + threadIdx.x;
    if (n >= N_TOT) return;
    g_rank[n] = atomicAdd(&g_cnt2[g_idx[n]], 1);
}

__global__ void scan_kernel() {
    __shared__ int s[K_CL];
    int tid = threadIdx.x;
    s[tid] = g_cnt2[tid];
    __syncthreads();
    #pragma unroll
    for (int off = 1; off < K_CL; off <<= 1) {
        int v = (tid >= off) ? s[tid - off] : 0;
        __syncthreads();
        s[tid] += v;
        __syncthreads();
    }
    g_off[tid] = s[tid] - g_cnt2[tid];   // exclusive
}

__global__ void scatter_kernel() {
    int n = blockIdx.x * blockDim.x + threadIdx.x;
    if (n >= N_TOT) return;
    g_order[g_off[g_idx[n]] + g_rank[n]] = n;
}

__global__ __launch_bounds__(256)
void gather_kernel(const float* __restrict__ X) {
    const int c  = blockIdx.x >> 2;
    const int qu = blockIdx.x & 3;
    const int d  = threadIdx.x;
    const int cnt  = g_cnt2[c];
    const int base = g_off[c];
    int beg = base + (cnt * qu) / 4;
    int end = base + (cnt * (qu + 1)) / 4;
    float a0 = 0.f, a1 = 0.f, a2 = 0.f, a3 = 0.f;
    int i = beg;
    for (; i + 3 < end; i += 4) {
        int n0 = g_order[i], n1 = g_order[i + 1];
        int n2 = g_order[i + 2], n3 = g_order[i + 3];
        a0 += X[(size_t)n0 * D_DIM + d];
        a1 += X[(size_t)n1 * D_DIM + d];
        a2 += X[(size_t)n2 * D_DIM + d];
        a3 += X[(size_t)n3 * D_DIM + d];
    }
    for (; i < end; ++i) a0 += X[(size_t)g_order[i] * D_DIM + d];
    g_part[qu][c][d] = (a0 + a1) + (a2 + a3);
}

__global__ void finalize_kernel(const float* __restrict__ C, float* __restrict__ outc) {
    int t = blockIdx.x * blockDim.x + threadIdx.x;
    if (t >= K_CL * D_DIM) return;
    int k = t >> 8, d = t & 255;
    float cnt = (float)g_cnt2[k];
    float sum = (g_part[0][k][d] + g_part[1][k][d])
              + (g_part[2][k][d] + g_part[3][k][d]);
    outc[t] = fmaf(0.9f, C[t], 0.1f * (sum / cnt));
}

// ---------------------------------------------------------------------------
extern "C" void kernel_launch(void* const* d_in, const int* in_sizes, int n_in,
                              void* d_out, int out_size) {
    const float* X = (const float*)d_in[0];
    const float* C = (const float*)d_in[1];
    float* out = (float*)d_out;
    (void)in_sizes; (void)n_in; (void)out_size;

    cudaFuncSetAttribute(argmin_mma, cudaFuncAttributeMaxDynamicSharedMemorySize,
                         SMEM_TOTAL);

    init_kernel<<<2, 256>>>(C);
    argmin_mma<<<N_TOT / MT, 256, SMEM_TOTAL>>>(X, C, out);
    refine_kernel<<<1024, 256>>>(X, C, out);
    rank_kernel<<<N_TOT / 256, 256>>>();
    scan_kernel<<<1, K_CL>>>();
    scatter_kernel<<<N_TOT / 256, 256>>>();
    gather_kernel<<<K_CL * 4, 256>>>(X);
    finalize_kernel<<<(K_CL * D_DIM) / 256, 256>>>(C, out + (size_t)N_TOT * K_CL);
}